// round 1
// baseline (speedup 1.0000x reference)
#include <cuda_runtime.h>
#include <math.h>

#define Bb   2
#define Nn   2048
#define Dd   1024
#define Hh   16
#define DHh  64
#define Mm   (Bb*Nn)      // 4096 rows
#define HDd  (Hh*DHh)     // 1024
#define LNEPS 1e-5f

// ---- device scratch (allocation-free per harness rules) ----
__device__ float g_xn[(size_t)Mm*Dd];
__device__ float g_cn[(size_t)Mm*Dd];
__device__ float g_q [(size_t)Mm*HDd];
__device__ float g_kv[(size_t)Mm*2*HDd];
__device__ float g_ao[(size_t)Mm*HDd];

// ============================================================
// Fused double LayerNorm: both LNs share mean/var of the row.
// grid = Mm rows, 256 threads, 4 elems/thread (D=1024)
// ============================================================
__global__ __launch_bounds__(256) void ln2_kernel(
    const float* __restrict__ x,
    const float* __restrict__ g1, const float* __restrict__ b1,
    const float* __restrict__ g2, const float* __restrict__ b2)
{
    const int row = blockIdx.x;
    const float* xr = x + (size_t)row * Dd;
    const int t = threadIdx.x;

    float v[4]; float s = 0.f, ss = 0.f;
#pragma unroll
    for (int i = 0; i < 4; i++) {
        float val = xr[t + i*256];
        v[i] = val; s += val; ss += val*val;
    }
#pragma unroll
    for (int o = 16; o > 0; o >>= 1) {
        s  += __shfl_xor_sync(0xffffffffu, s,  o);
        ss += __shfl_xor_sync(0xffffffffu, ss, o);
    }
    __shared__ float rs[8], rss[8];
    const int w = t >> 5, l = t & 31;
    if (l == 0) { rs[w] = s; rss[w] = ss; }
    __syncthreads();
    if (t == 0) {
        float a = 0.f, c = 0.f;
        for (int i = 0; i < 8; i++) { a += rs[i]; c += rss[i]; }
        rs[0] = a; rss[0] = c;
    }
    __syncthreads();
    const float mean = rs[0] * (1.f/Dd);
    const float var  = rss[0] * (1.f/Dd) - mean*mean;
    const float rstd = rsqrtf(var + LNEPS);

    float* xn = g_xn + (size_t)row*Dd;
    float* cn = g_cn + (size_t)row*Dd;
#pragma unroll
    for (int i = 0; i < 4; i++) {
        int idx = t + i*256;
        float nv = (v[i] - mean) * rstd;
        xn[idx] = nv * g1[idx] + b1[idx];
        cn[idx] = nv * g2[idx] + b2[idx];
    }
}

// ============================================================
// Generic fp32 GEMM: C[M,Nc] = A[M,K] @ W[K,Nc]
// 64x64 tile, 256 threads (16x16), 4x4 micro-tile, k-step 16.
// M, Nc multiples of 64; K multiple of 16. row0/col0 from blockIdx.
// ============================================================
__global__ __launch_bounds__(256) void gemm_kernel(
    const float* __restrict__ A, const float* __restrict__ W,
    float* __restrict__ C, int K, int Nc)
{
    __shared__ float As[16][64];   // As[k][r]
    __shared__ float Ws[16][64];   // Ws[k][c]

    const int t  = threadIdx.x;
    const int tx = t & 15, ty = t >> 4;
    const int row0 = blockIdx.y * 64;
    const int col0 = blockIdx.x * 64;

    float acc[4][4];
#pragma unroll
    for (int i = 0; i < 4; i++)
#pragma unroll
        for (int j = 0; j < 4; j++) acc[i][j] = 0.f;

    // load mappings
    const int ar = t >> 2, ac = (t & 3) * 4;     // A tile: 64 rows x 16 k
    const int wr = t >> 4, wc = (t & 15) * 4;    // W tile: 16 k x 64 cols

    for (int kk = 0; kk < K; kk += 16) {
        float4 av = *(const float4*)(A + (size_t)(row0 + ar)*K + kk + ac);
        float4 wv = *(const float4*)(W + (size_t)(kk + wr)*Nc + col0 + wc);
        As[ac+0][ar] = av.x; As[ac+1][ar] = av.y;
        As[ac+2][ar] = av.z; As[ac+3][ar] = av.w;
        *(float4*)&Ws[wr][wc] = wv;
        __syncthreads();
#pragma unroll
        for (int k = 0; k < 16; k++) {
            float4 a4 = *(const float4*)&As[k][ty*4];
            float4 b4 = *(const float4*)&Ws[k][tx*4];
            float a[4] = {a4.x, a4.y, a4.z, a4.w};
            float b[4] = {b4.x, b4.y, b4.z, b4.w};
#pragma unroll
            for (int i = 0; i < 4; i++)
#pragma unroll
                for (int j = 0; j < 4; j++)
                    acc[i][j] += a[i] * b[j];
        }
        __syncthreads();
    }

#pragma unroll
    for (int i = 0; i < 4; i++) {
        float4 ov = make_float4(acc[i][0], acc[i][1], acc[i][2], acc[i][3]);
        *(float4*)(C + (size_t)(row0 + ty*4 + i)*Nc + col0 + tx*4) = ov;
    }
}

// ============================================================
// Causal flash attention, fp32.
// grid = (N/64 q-tiles, B*H), 256 threads (16x16), 4x4 micro.
// Smem (dynamic): Qt[d][i], Kt[d][j], Vs[j][d], Ps[i][j], pad 68.
// ============================================================
#define FPAD 68
__global__ __launch_bounds__(256) void flash_kernel(
    const float* __restrict__ q, const float* __restrict__ kv,
    float* __restrict__ o)
{
    extern __shared__ float sm[];
    float* Qt = sm;                  // [64][FPAD]  Qt[d*FPAD + i]
    float* Kt = sm + 64*FPAD;        // Kt[d*FPAD + j]
    float* Vs = sm + 2*64*FPAD;      // Vs[j*FPAD + d]
    float* Ps = sm + 3*64*FPAD;      // Ps[i*FPAD + j]

    const int t  = threadIdx.x;
    const int tx = t & 15, ty = t >> 4;
    const int it = blockIdx.x;
    const int bh = blockIdx.y;
    const int b  = bh >> 4, h = bh & 15;
    const int row0 = it * 64;
    const float scale = 0.125f;      // 1/sqrt(64)

    // Load Q tile transposed (float4 global reads)
    for (int e = t; e < 1024; e += 256) {
        int i = e >> 4, d4 = (e & 15) * 4;
        float4 v = *(const float4*)(q + (size_t)(b*Nn + row0 + i)*HDd + h*DHh + d4);
        Qt[(d4+0)*FPAD + i] = v.x;
        Qt[(d4+1)*FPAD + i] = v.y;
        Qt[(d4+2)*FPAD + i] = v.z;
        Qt[(d4+3)*FPAD + i] = v.w;
    }

    float m_prev[4], lsum[4], acc[4][4];
#pragma unroll
    for (int i = 0; i < 4; i++) {
        m_prev[i] = -1e30f; lsum[i] = 0.f;
#pragma unroll
        for (int j = 0; j < 4; j++) acc[i][j] = 0.f;
    }

    for (int jt = 0; jt <= it; jt++) {
        const int col0 = jt * 64;
        __syncthreads();   // protect Kt/Vs/Ps reuse + Qt first use
        for (int e = t; e < 1024; e += 256) {
            int j = e >> 4, d4 = (e & 15) * 4;
            size_t base = (size_t)(b*Nn + col0 + j)*(2*HDd) + h*DHh;
            float4 kvk = *(const float4*)(kv + base + d4);
            Kt[(d4+0)*FPAD + j] = kvk.x;
            Kt[(d4+1)*FPAD + j] = kvk.y;
            Kt[(d4+2)*FPAD + j] = kvk.z;
            Kt[(d4+3)*FPAD + j] = kvk.w;
            float4 vvv = *(const float4*)(kv + base + HDd + d4);
            *(float4*)(Vs + j*FPAD + d4) = vvv;
        }
        __syncthreads();

        // S = Q @ K^T (4x4 micro per thread)
        float s[4][4];
#pragma unroll
        for (int i = 0; i < 4; i++)
#pragma unroll
            for (int j = 0; j < 4; j++) s[i][j] = 0.f;
        for (int d = 0; d < 64; d++) {
            float4 a4 = *(const float4*)(Qt + d*FPAD + ty*4);
            float4 b4 = *(const float4*)(Kt + d*FPAD + tx*4);
            float a[4] = {a4.x, a4.y, a4.z, a4.w};
            float bbr[4] = {b4.x, b4.y, b4.z, b4.w};
#pragma unroll
            for (int i = 0; i < 4; i++)
#pragma unroll
                for (int j = 0; j < 4; j++)
                    s[i][j] += a[i] * bbr[j];
        }
        // scale + causal mask (only needed on the diagonal tile)
#pragma unroll
        for (int i = 0; i < 4; i++)
#pragma unroll
            for (int j = 0; j < 4; j++) {
                s[i][j] *= scale;
                if (jt == it && (tx*4 + j) > (ty*4 + i)) s[i][j] = -1e30f;
            }

        // online softmax (row = 16 threads sharing ty; lanes ty*16..+15)
        float p[4][4];
#pragma unroll
        for (int i = 0; i < 4; i++) {
            float rm = fmaxf(fmaxf(s[i][0], s[i][1]), fmaxf(s[i][2], s[i][3]));
            rm = fmaxf(rm, __shfl_xor_sync(0xffffffffu, rm, 1));
            rm = fmaxf(rm, __shfl_xor_sync(0xffffffffu, rm, 2));
            rm = fmaxf(rm, __shfl_xor_sync(0xffffffffu, rm, 4));
            rm = fmaxf(rm, __shfl_xor_sync(0xffffffffu, rm, 8));
            float mnew = fmaxf(m_prev[i], rm);
            float rsum = 0.f;
#pragma unroll
            for (int j = 0; j < 4; j++) {
                p[i][j] = __expf(s[i][j] - mnew);
                rsum += p[i][j];
            }
            rsum += __shfl_xor_sync(0xffffffffu, rsum, 1);
            rsum += __shfl_xor_sync(0xffffffffu, rsum, 2);
            rsum += __shfl_xor_sync(0xffffffffu, rsum, 4);
            rsum += __shfl_xor_sync(0xffffffffu, rsum, 8);
            float alpha = __expf(m_prev[i] - mnew);
            lsum[i] = lsum[i] * alpha + rsum;
            m_prev[i] = mnew;
#pragma unroll
            for (int j = 0; j < 4; j++) acc[i][j] *= alpha;
        }

        // write P tile (natural layout, float4 rows)
#pragma unroll
        for (int i = 0; i < 4; i++)
            *(float4*)(Ps + (ty*4 + i)*FPAD + tx*4) =
                make_float4(p[i][0], p[i][1], p[i][2], p[i][3]);
        __syncthreads();

        // O += P @ V
        for (int j = 0; j < 64; j++) {
            float4 b4 = *(const float4*)(Vs + j*FPAD + tx*4);
            float bbr[4] = {b4.x, b4.y, b4.z, b4.w};
#pragma unroll
            for (int i = 0; i < 4; i++) {
                float a = Ps[(ty*4 + i)*FPAD + j];   // broadcast across tx
                acc[i][0] += a * bbr[0];
                acc[i][1] += a * bbr[1];
                acc[i][2] += a * bbr[2];
                acc[i][3] += a * bbr[3];
            }
        }
    }

    // epilogue: normalize, write [b, n, h*DH + d] layout
#pragma unroll
    for (int i = 0; i < 4; i++) {
        float inv = 1.f / lsum[i];
        float4 ov = make_float4(acc[i][0]*inv, acc[i][1]*inv,
                                acc[i][2]*inv, acc[i][3]*inv);
        *(float4*)(o + (size_t)(b*Nn + row0 + ty*4 + i)*HDd + h*DHh + tx*4) = ov;
    }
}

// ============================================================
// launch
// ============================================================
extern "C" void kernel_launch(void* const* d_in, const int* in_sizes, int n_in,
                              void* d_out, int out_size)
{
    const float* x     = (const float*)d_in[0];
    const float* ln_g  = (const float*)d_in[1];
    const float* ln_b  = (const float*)d_in[2];
    const float* lnc_g = (const float*)d_in[3];
    const float* lnc_b = (const float*)d_in[4];
    const float* Wq    = (const float*)d_in[5];
    const float* Wkv   = (const float*)d_in[6];
    const float* Wo    = (const float*)d_in[7];
    float* out = (float*)d_out;

    float *xn, *cn, *qp, *kvp, *aop;
    cudaGetSymbolAddress((void**)&xn,  g_xn);
    cudaGetSymbolAddress((void**)&cn,  g_cn);
    cudaGetSymbolAddress((void**)&qp,  g_q);
    cudaGetSymbolAddress((void**)&kvp, g_kv);
    cudaGetSymbolAddress((void**)&aop, g_ao);

    const int FSM = 4 * 64 * FPAD * (int)sizeof(float);  // 69632 B
    cudaFuncSetAttribute(flash_kernel,
                         cudaFuncAttributeMaxDynamicSharedMemorySize, FSM);

    // 1) fused double layernorm
    ln2_kernel<<<Mm, 256>>>(x, ln_g, ln_b, lnc_g, lnc_b);
    // 2) q = xn @ Wq            [4096,1024] @ [1024,1024]
    gemm_kernel<<<dim3(HDd/64, Mm/64), 256>>>(xn, Wq, qp, Dd, HDd);
    // 3) kv = cn @ Wkv          [4096,1024] @ [1024,2048]
    gemm_kernel<<<dim3(2*HDd/64, Mm/64), 256>>>(cn, Wkv, kvp, Dd, 2*HDd);
    // 4) causal flash attention
    flash_kernel<<<dim3(Nn/64, Bb*Hh), 256, FSM>>>(qp, kvp, aop);
    // 5) out = ao @ Wo          [4096,1024] @ [1024,1024]
    gemm_kernel<<<dim3(Dd/64, Mm/64), 256>>>(aop, Wo, out, HDd, Dd);
}

// round 3
// speedup vs baseline: 1.9276x; 1.9276x over previous
#include <cuda_runtime.h>
#include <cuda_fp16.h>
#include <math.h>
#include <cstdint>

#define Bb   2
#define Nn   2048
#define Dd   1024
#define Hh   16
#define DHh  64
#define Mm   (Bb*Nn)      // 4096 rows
#define HDd  (Hh*DHh)     // 1024
#define KDIM 1024         // all projection GEMMs have K = 1024
#define LNEPS 1e-5f

// ---- device scratch (allocation-free per harness rules) ----
__device__ __half g_xn[(size_t)Mm*Dd];
__device__ __half g_cn[(size_t)Mm*Dd];
__device__ float  g_q [(size_t)Mm*HDd];
__device__ float  g_kv[(size_t)Mm*2*HDd];
__device__ __half g_ao[(size_t)Mm*HDd];
__device__ __half g_wT[(size_t)2*HDd*Dd];   // transposed half weights (4 MB)

__device__ __forceinline__ uint32_t smem_u32(const void* p) {
    uint32_t a;
    asm("{ .reg .u64 t; cvta.to.shared.u64 t, %1; cvt.u32.u64 %0, t; }"
        : "=r"(a) : "l"(p));
    return a;
}

// ============================================================
// Fused double LayerNorm -> half outputs
// ============================================================
__global__ __launch_bounds__(256) void ln2_kernel(
    const float* __restrict__ x,
    const float* __restrict__ g1, const float* __restrict__ b1,
    const float* __restrict__ g2, const float* __restrict__ b2)
{
    const int row = blockIdx.x;
    const float* xr = x + (size_t)row * Dd;
    const int t = threadIdx.x;

    float v[4]; float s = 0.f, ss = 0.f;
#pragma unroll
    for (int i = 0; i < 4; i++) {
        float val = xr[t + i*256];
        v[i] = val; s += val; ss += val*val;
    }
#pragma unroll
    for (int o = 16; o > 0; o >>= 1) {
        s  += __shfl_xor_sync(0xffffffffu, s,  o);
        ss += __shfl_xor_sync(0xffffffffu, ss, o);
    }
    __shared__ float rs[8], rss[8];
    const int w = t >> 5, l = t & 31;
    if (l == 0) { rs[w] = s; rss[w] = ss; }
    __syncthreads();
    if (t == 0) {
        float a = 0.f, c = 0.f;
        for (int i = 0; i < 8; i++) { a += rs[i]; c += rss[i]; }
        rs[0] = a; rss[0] = c;
    }
    __syncthreads();
    const float mean = rs[0] * (1.f/Dd);
    const float var  = rss[0] * (1.f/Dd) - mean*mean;
    const float rstd = rsqrtf(var + LNEPS);

    __half* xn = g_xn + (size_t)row*Dd;
    __half* cn = g_cn + (size_t)row*Dd;
#pragma unroll
    for (int i = 0; i < 4; i++) {
        int idx = t + i*256;
        float nv = (v[i] - mean) * rstd;
        xn[idx] = __float2half_rn(nv * g1[idx] + b1[idx]);
        cn[idx] = __float2half_rn(nv * g2[idx] + b2[idx]);
    }
}

// ============================================================
// Weight transpose + fp32->fp16: WT[n][k] = half(W[k][n])
// grid (Nc/32, K/32), block (32,8)
// ============================================================
__global__ __launch_bounds__(256) void transpose_h(
    const float* __restrict__ W, __half* __restrict__ WT, int K, int Nc)
{
    __shared__ float tile[32][33];
    const int bn = blockIdx.x * 32, bk = blockIdx.y * 32;
    const int x = threadIdx.x, y = threadIdx.y;
#pragma unroll
    for (int i = 0; i < 32; i += 8)
        tile[y + i][x] = W[(size_t)(bk + y + i) * Nc + bn + x];
    __syncthreads();
#pragma unroll
    for (int i = 0; i < 32; i += 8)
        WT[(size_t)(bn + y + i) * K + bk + x] = __float2half_rn(tile[x][y + i]);
}

// ============================================================
// fp16 HMMA GEMM: C[M,Nc](f32) = Ah[M,1024](half) @ WT[Nc,1024]^T
// CTA 128x128, 8 warps (2x4), warp tile 64x32, mma m16n8k16.
// K-chunk 32, double-buffered smem, register prefetch.
// smem rows padded to 40 halfs (80B) -> conflict-free ldmatrix.
// ============================================================
#define ROWB 40                    // halfs per smem row (80 bytes)
#define ABUF (128*ROWB*2)          // bytes per buffer (10240)

__global__ __launch_bounds__(256) void gemm_hmma(
    const __half* __restrict__ Ah, const __half* __restrict__ BTh,
    float* __restrict__ C, int Nc)
{
    __shared__ __half As[2*128*ROWB];
    __shared__ __half Bs[2*128*ROWB];

    const int t = threadIdx.x;
    const int lane = t & 31, wid = t >> 5;
    const int wm = wid >> 2, wn = wid & 3;       // warp grid 2 (m) x 4 (n)
    const int row0 = blockIdx.y * 128, col0 = blockIdx.x * 128;

    const int r0 = t >> 2, c8 = t & 3;           // load mapping
    const __half* Aptr = Ah  + (size_t)(row0 + r0) * KDIM + c8 * 8;
    const __half* Bptr = BTh + (size_t)(col0 + r0) * KDIM + c8 * 8;
    const uint32_t st_off = (uint32_t)(r0 * 80 + c8 * 16);   // bytes in buffer

    const uint32_t asb = smem_u32(As);
    const uint32_t bsb = smem_u32(Bs);

    // ldmatrix per-lane offsets (bytes, within a buffer)
    const int ll = lane & 15;
    const uint32_t a_l_off = (uint32_t)((wm*64 + (lane & 7) + ((lane >> 3) & 1) * 8) * 80
                                        + ((lane >> 4) & 1) * 16);
    const uint32_t b_l_off = (uint32_t)((wn*32 + (ll & 7)) * 80 + ((ll >> 3) & 1) * 16);

    float c[4][4][4];
#pragma unroll
    for (int i = 0; i < 4; i++)
#pragma unroll
        for (int j = 0; j < 4; j++)
#pragma unroll
            for (int q = 0; q < 4; q++) c[i][j][q] = 0.f;

    uint4 pa0, pa1, pb0, pb1;
    // prolog: load chunk 0
    pa0 = *(const uint4*)(Aptr);
    pa1 = *(const uint4*)(Aptr + (size_t)64 * KDIM);
    pb0 = *(const uint4*)(Bptr);
    pb1 = *(const uint4*)(Bptr + (size_t)64 * KDIM);
    *(uint4*)((char*)As + st_off)            = pa0;
    *(uint4*)((char*)As + st_off + 64*80)    = pa1;
    *(uint4*)((char*)Bs + st_off)            = pb0;
    *(uint4*)((char*)Bs + st_off + 64*80)    = pb1;
    __syncthreads();

    for (int ch = 0; ch < 32; ch++) {
        const int s = ch & 1;
        if (ch < 31) {
            const __half* Ap = Aptr + (ch + 1) * 32;
            const __half* Bp = Bptr + (ch + 1) * 32;
            pa0 = *(const uint4*)(Ap);
            pa1 = *(const uint4*)(Ap + (size_t)64 * KDIM);
            pb0 = *(const uint4*)(Bp);
            pb1 = *(const uint4*)(Bp + (size_t)64 * KDIM);
        }

        const uint32_t ab = asb + s * ABUF + a_l_off;
        const uint32_t bb = bsb + s * ABUF + b_l_off;
#pragma unroll
        for (int ks = 0; ks < 2; ks++) {
            uint32_t a[4][4];
            uint32_t b[4][2];
#pragma unroll
            for (int im = 0; im < 4; im++)
                asm volatile("ldmatrix.sync.aligned.m8n8.x4.shared.b16 {%0,%1,%2,%3}, [%4];"
                    : "=r"(a[im][0]), "=r"(a[im][1]), "=r"(a[im][2]), "=r"(a[im][3])
                    : "r"(ab + im * (16*80) + ks * 32));
#pragma unroll
            for (int jn = 0; jn < 4; jn++)
                asm volatile("ldmatrix.sync.aligned.m8n8.x2.shared.b16 {%0,%1}, [%2];"
                    : "=r"(b[jn][0]), "=r"(b[jn][1])
                    : "r"(bb + jn * (8*80) + ks * 32));
#pragma unroll
            for (int im = 0; im < 4; im++)
#pragma unroll
                for (int jn = 0; jn < 4; jn++)
                    asm volatile(
                        "mma.sync.aligned.m16n8k16.row.col.f32.f16.f16.f32 "
                        "{%0,%1,%2,%3}, {%4,%5,%6,%7}, {%8,%9}, {%0,%1,%2,%3};"
                        : "+f"(c[im][jn][0]), "+f"(c[im][jn][1]),
                          "+f"(c[im][jn][2]), "+f"(c[im][jn][3])
                        : "r"(a[im][0]), "r"(a[im][1]), "r"(a[im][2]), "r"(a[im][3]),
                          "r"(b[jn][0]), "r"(b[jn][1]));
        }

        if (ch < 31) {
            const int s2 = s ^ 1;
            *(uint4*)((char*)As + s2*ABUF + st_off)         = pa0;
            *(uint4*)((char*)As + s2*ABUF + st_off + 64*80) = pa1;
            *(uint4*)((char*)Bs + s2*ABUF + st_off)         = pb0;
            *(uint4*)((char*)Bs + s2*ABUF + st_off + 64*80) = pb1;
            __syncthreads();
        }
    }

    // epilogue: direct float2 stores
    const int g  = lane >> 2;
    const int tq = lane & 3;
#pragma unroll
    for (int im = 0; im < 4; im++) {
#pragma unroll
        for (int jn = 0; jn < 4; jn++) {
            const int row = row0 + wm*64 + im*16 + g;
            const int col = col0 + wn*32 + jn*8 + tq*2;
            *(float2*)(C + (size_t)row * Nc + col) =
                make_float2(c[im][jn][0], c[im][jn][1]);
            *(float2*)(C + (size_t)(row + 8) * Nc + col) =
                make_float2(c[im][jn][2], c[im][jn][3]);
        }
    }
}

// ============================================================
// Causal flash attention, fp32 compute, half output
// ============================================================
#define FPAD 68
__global__ __launch_bounds__(256) void flash_kernel(
    const float* __restrict__ q, const float* __restrict__ kv,
    __half* __restrict__ o)
{
    extern __shared__ float smf[];
    float* Qt = smf;                  // [64][FPAD]  Qt[d*FPAD + i]
    float* Kt = smf + 64*FPAD;
    float* Vs = smf + 2*64*FPAD;
    float* Ps = smf + 3*64*FPAD;

    const int t  = threadIdx.x;
    const int tx = t & 15, ty = t >> 4;
    const int it = blockIdx.x;
    const int bh = blockIdx.y;
    const int b  = bh >> 4, h = bh & 15;
    const int row0 = it * 64;
    const float scale = 0.125f;

    for (int e = t; e < 1024; e += 256) {
        int i = e >> 4, d4 = (e & 15) * 4;
        float4 v = *(const float4*)(q + (size_t)(b*Nn + row0 + i)*HDd + h*DHh + d4);
        Qt[(d4+0)*FPAD + i] = v.x;
        Qt[(d4+1)*FPAD + i] = v.y;
        Qt[(d4+2)*FPAD + i] = v.z;
        Qt[(d4+3)*FPAD + i] = v.w;
    }

    float m_prev[4], lsum[4], acc[4][4];
#pragma unroll
    for (int i = 0; i < 4; i++) {
        m_prev[i] = -1e30f; lsum[i] = 0.f;
#pragma unroll
        for (int j = 0; j < 4; j++) acc[i][j] = 0.f;
    }

    for (int jt = 0; jt <= it; jt++) {
        const int col0 = jt * 64;
        __syncthreads();
        for (int e = t; e < 1024; e += 256) {
            int j = e >> 4, d4 = (e & 15) * 4;
            size_t base = (size_t)(b*Nn + col0 + j)*(2*HDd) + h*DHh;
            float4 kvk = *(const float4*)(kv + base + d4);
            Kt[(d4+0)*FPAD + j] = kvk.x;
            Kt[(d4+1)*FPAD + j] = kvk.y;
            Kt[(d4+2)*FPAD + j] = kvk.z;
            Kt[(d4+3)*FPAD + j] = kvk.w;
            float4 vvv = *(const float4*)(kv + base + HDd + d4);
            *(float4*)(Vs + j*FPAD + d4) = vvv;
        }
        __syncthreads();

        float s[4][4];
#pragma unroll
        for (int i = 0; i < 4; i++)
#pragma unroll
            for (int j = 0; j < 4; j++) s[i][j] = 0.f;
        for (int d = 0; d < 64; d++) {
            float4 a4 = *(const float4*)(Qt + d*FPAD + ty*4);
            float4 b4 = *(const float4*)(Kt + d*FPAD + tx*4);
            float a[4] = {a4.x, a4.y, a4.z, a4.w};
            float bbr[4] = {b4.x, b4.y, b4.z, b4.w};
#pragma unroll
            for (int i = 0; i < 4; i++)
#pragma unroll
                for (int j = 0; j < 4; j++)
                    s[i][j] += a[i] * bbr[j];
        }
#pragma unroll
        for (int i = 0; i < 4; i++)
#pragma unroll
            for (int j = 0; j < 4; j++) {
                s[i][j] *= scale;
                if (jt == it && (tx*4 + j) > (ty*4 + i)) s[i][j] = -1e30f;
            }

        float p[4][4];
#pragma unroll
        for (int i = 0; i < 4; i++) {
            float rm = fmaxf(fmaxf(s[i][0], s[i][1]), fmaxf(s[i][2], s[i][3]));
            rm = fmaxf(rm, __shfl_xor_sync(0xffffffffu, rm, 1));
            rm = fmaxf(rm, __shfl_xor_sync(0xffffffffu, rm, 2));
            rm = fmaxf(rm, __shfl_xor_sync(0xffffffffu, rm, 4));
            rm = fmaxf(rm, __shfl_xor_sync(0xffffffffu, rm, 8));
            float mnew = fmaxf(m_prev[i], rm);
            float rsum = 0.f;
#pragma unroll
            for (int j = 0; j < 4; j++) {
                p[i][j] = __expf(s[i][j] - mnew);
                rsum += p[i][j];
            }
            rsum += __shfl_xor_sync(0xffffffffu, rsum, 1);
            rsum += __shfl_xor_sync(0xffffffffu, rsum, 2);
            rsum += __shfl_xor_sync(0xffffffffu, rsum, 4);
            rsum += __shfl_xor_sync(0xffffffffu, rsum, 8);
            float alpha = __expf(m_prev[i] - mnew);
            lsum[i] = lsum[i] * alpha + rsum;
            m_prev[i] = mnew;
#pragma unroll
            for (int j = 0; j < 4; j++) acc[i][j] *= alpha;
        }

#pragma unroll
        for (int i = 0; i < 4; i++)
            *(float4*)(Ps + (ty*4 + i)*FPAD + tx*4) =
                make_float4(p[i][0], p[i][1], p[i][2], p[i][3]);
        __syncthreads();

        for (int j = 0; j < 64; j++) {
            float4 b4 = *(const float4*)(Vs + j*FPAD + tx*4);
            float bbr[4] = {b4.x, b4.y, b4.z, b4.w};
#pragma unroll
            for (int i = 0; i < 4; i++) {
                float a = Ps[(ty*4 + i)*FPAD + j];
                acc[i][0] += a * bbr[0];
                acc[i][1] += a * bbr[1];
                acc[i][2] += a * bbr[2];
                acc[i][3] += a * bbr[3];
            }
        }
    }

#pragma unroll
    for (int i = 0; i < 4; i++) {
        float inv = 1.f / lsum[i];
        size_t base = (size_t)(b*Nn + row0 + ty*4 + i)*HDd + h*DHh + tx*4;
        __half2 p0 = __floats2half2_rn(acc[i][0]*inv, acc[i][1]*inv);
        __half2 p1 = __floats2half2_rn(acc[i][2]*inv, acc[i][3]*inv);
        *(__half2*)(o + base)     = p0;
        *(__half2*)(o + base + 2) = p1;
    }
}

// ============================================================
// launch
// ============================================================
extern "C" void kernel_launch(void* const* d_in, const int* in_sizes, int n_in,
                              void* d_out, int out_size)
{
    const float* x     = (const float*)d_in[0];
    const float* ln_g  = (const float*)d_in[1];
    const float* ln_b  = (const float*)d_in[2];
    const float* lnc_g = (const float*)d_in[3];
    const float* lnc_b = (const float*)d_in[4];
    const float* Wq    = (const float*)d_in[5];
    const float* Wkv   = (const float*)d_in[6];
    const float* Wo    = (const float*)d_in[7];
    float* out = (float*)d_out;

    __half *xn, *cn, *aop, *wT;
    float *qp, *kvp;
    cudaGetSymbolAddress((void**)&xn,  g_xn);
    cudaGetSymbolAddress((void**)&cn,  g_cn);
    cudaGetSymbolAddress((void**)&qp,  g_q);
    cudaGetSymbolAddress((void**)&kvp, g_kv);
    cudaGetSymbolAddress((void**)&aop, g_ao);
    cudaGetSymbolAddress((void**)&wT,  g_wT);

    const int FSM = 4 * 64 * FPAD * (int)sizeof(float);
    cudaFuncSetAttribute(flash_kernel,
                         cudaFuncAttributeMaxDynamicSharedMemorySize, FSM);

    // 1) fused double layernorm (half outputs)
    ln2_kernel<<<Mm, 256>>>(x, ln_g, ln_b, lnc_g, lnc_b);

    // 2) q = xn @ Wq
    transpose_h<<<dim3(HDd/32, Dd/32), dim3(32, 8)>>>(Wq, wT, Dd, HDd);
    gemm_hmma<<<dim3(HDd/128, Mm/128), 256>>>(xn, wT, qp, HDd);

    // 3) kv = cn @ Wkv
    transpose_h<<<dim3(2*HDd/32, Dd/32), dim3(32, 8)>>>(Wkv, wT, Dd, 2*HDd);
    gemm_hmma<<<dim3(2*HDd/128, Mm/128), 256>>>(cn, wT, kvp, 2*HDd);

    // 4) causal flash attention (fp32 compute, half output)
    flash_kernel<<<dim3(Nn/64, Bb*Hh), 256, FSM>>>(qp, kvp, aop);

    // 5) out = ao @ Wo
    transpose_h<<<dim3(Dd/32, HDd/32), dim3(32, 8)>>>(Wo, wT, HDd, Dd);
    gemm_hmma<<<dim3(Dd/128, Mm/128), 256>>>(aop, wT, out, Dd);
}

// round 4
// speedup vs baseline: 5.6652x; 2.9391x over previous
#include <cuda_runtime.h>
#include <cuda_fp16.h>
#include <math.h>
#include <cstdint>

#define Bb   2
#define Nn   2048
#define Dd   1024
#define Hh   16
#define DHh  64
#define Mm   (Bb*Nn)      // 4096 rows
#define HDd  (Hh*DHh)     // 1024
#define KDIM 1024
#define LNEPS 1e-5f

// ---- device scratch ----
__device__ __half g_xn[(size_t)Mm*Dd];
__device__ __half g_cn[(size_t)Mm*Dd];
__device__ __half g_q [(size_t)Mm*HDd];
__device__ __half g_kv[(size_t)Mm*2*HDd];
__device__ __half g_ao[(size_t)Mm*HDd];
__device__ __half g_wT[(size_t)2*HDd*Dd];

__device__ __forceinline__ uint32_t smem_u32(const void* p) {
    uint32_t a;
    asm("{ .reg .u64 t; cvta.to.shared.u64 t, %1; cvt.u32.u64 %0, t; }"
        : "=r"(a) : "l"(p));
    return a;
}

#define MMA16816(d, a, b0, b1) \
    asm volatile("mma.sync.aligned.m16n8k16.row.col.f32.f16.f16.f32 " \
        "{%0,%1,%2,%3}, {%4,%5,%6,%7}, {%8,%9}, {%0,%1,%2,%3};" \
        : "+f"((d)[0]), "+f"((d)[1]), "+f"((d)[2]), "+f"((d)[3]) \
        : "r"((a)[0]), "r"((a)[1]), "r"((a)[2]), "r"((a)[3]), \
          "r"(b0), "r"(b1))

#define LDSM4(r, addr) \
    asm volatile("ldmatrix.sync.aligned.m8n8.x4.shared.b16 {%0,%1,%2,%3}, [%4];" \
        : "=r"((r)[0]), "=r"((r)[1]), "=r"((r)[2]), "=r"((r)[3]) : "r"(addr))
#define LDSM4T(r, addr) \
    asm volatile("ldmatrix.sync.aligned.m8n8.x4.trans.shared.b16 {%0,%1,%2,%3}, [%4];" \
        : "=r"((r)[0]), "=r"((r)[1]), "=r"((r)[2]), "=r"((r)[3]) : "r"(addr))

__device__ __forceinline__ uint32_t pack_h2(float a, float b) {
    __half2 h = __floats2half2_rn(a, b);
    return *(uint32_t*)&h;
}

// ============================================================
// Fused double LayerNorm -> half outputs
// ============================================================
__global__ __launch_bounds__(256) void ln2_kernel(
    const float* __restrict__ x,
    const float* __restrict__ g1, const float* __restrict__ b1,
    const float* __restrict__ g2, const float* __restrict__ b2)
{
    const int row = blockIdx.x;
    const float* xr = x + (size_t)row * Dd;
    const int t = threadIdx.x;

    float v[4]; float s = 0.f, ss = 0.f;
#pragma unroll
    for (int i = 0; i < 4; i++) {
        float val = xr[t + i*256];
        v[i] = val; s += val; ss += val*val;
    }
#pragma unroll
    for (int o = 16; o > 0; o >>= 1) {
        s  += __shfl_xor_sync(0xffffffffu, s,  o);
        ss += __shfl_xor_sync(0xffffffffu, ss, o);
    }
    __shared__ float rs[8], rss[8];
    const int w = t >> 5, l = t & 31;
    if (l == 0) { rs[w] = s; rss[w] = ss; }
    __syncthreads();
    if (t == 0) {
        float a = 0.f, c = 0.f;
        for (int i = 0; i < 8; i++) { a += rs[i]; c += rss[i]; }
        rs[0] = a; rss[0] = c;
    }
    __syncthreads();
    const float mean = rs[0] * (1.f/Dd);
    const float var  = rss[0] * (1.f/Dd) - mean*mean;
    const float rstd = rsqrtf(var + LNEPS);

    __half* xn = g_xn + (size_t)row*Dd;
    __half* cn = g_cn + (size_t)row*Dd;
#pragma unroll
    for (int i = 0; i < 4; i++) {
        int idx = t + i*256;
        float nv = (v[i] - mean) * rstd;
        xn[idx] = __float2half_rn(nv * g1[idx] + b1[idx]);
        cn[idx] = __float2half_rn(nv * g2[idx] + b2[idx]);
    }
}

// ============================================================
// Weight transpose + fp32->fp16
// ============================================================
__global__ __launch_bounds__(256) void transpose_h(
    const float* __restrict__ W, __half* __restrict__ WT, int K, int Nc)
{
    __shared__ float tile[32][33];
    const int bn = blockIdx.x * 32, bk = blockIdx.y * 32;
    const int x = threadIdx.x, y = threadIdx.y;
#pragma unroll
    for (int i = 0; i < 32; i += 8)
        tile[y + i][x] = W[(size_t)(bk + y + i) * Nc + bn + x];
    __syncthreads();
#pragma unroll
    for (int i = 0; i < 32; i += 8)
        WT[(size_t)(bn + y + i) * K + bk + x] = __float2half_rn(tile[x][y + i]);
}

// ============================================================
// fp16 HMMA GEMM, templated output (float or half)
// ============================================================
#define ROWB 40
#define ABUF (128*ROWB*2)

template <typename OT>
__global__ __launch_bounds__(256) void gemm_hmma(
    const __half* __restrict__ Ah, const __half* __restrict__ BTh,
    OT* __restrict__ C, int Nc)
{
    __shared__ __half As[2*128*ROWB];
    __shared__ __half Bs[2*128*ROWB];

    const int t = threadIdx.x;
    const int lane = t & 31, wid = t >> 5;
    const int wm = wid >> 2, wn = wid & 3;
    const int row0 = blockIdx.y * 128, col0 = blockIdx.x * 128;

    const int r0 = t >> 2, c8 = t & 3;
    const __half* Aptr = Ah  + (size_t)(row0 + r0) * KDIM + c8 * 8;
    const __half* Bptr = BTh + (size_t)(col0 + r0) * KDIM + c8 * 8;
    const uint32_t st_off = (uint32_t)(r0 * 80 + c8 * 16);

    const uint32_t asb = smem_u32(As);
    const uint32_t bsb = smem_u32(Bs);

    const int ll = lane & 15;
    const uint32_t a_l_off = (uint32_t)((wm*64 + (lane & 7) + ((lane >> 3) & 1) * 8) * 80
                                        + ((lane >> 4) & 1) * 16);
    const uint32_t b_l_off = (uint32_t)((wn*32 + (ll & 7)) * 80 + ((ll >> 3) & 1) * 16);

    float c[4][4][4];
#pragma unroll
    for (int i = 0; i < 4; i++)
#pragma unroll
        for (int j = 0; j < 4; j++)
#pragma unroll
            for (int q = 0; q < 4; q++) c[i][j][q] = 0.f;

    uint4 pa0, pa1, pb0, pb1;
    pa0 = *(const uint4*)(Aptr);
    pa1 = *(const uint4*)(Aptr + (size_t)64 * KDIM);
    pb0 = *(const uint4*)(Bptr);
    pb1 = *(const uint4*)(Bptr + (size_t)64 * KDIM);
    *(uint4*)((char*)As + st_off)            = pa0;
    *(uint4*)((char*)As + st_off + 64*80)    = pa1;
    *(uint4*)((char*)Bs + st_off)            = pb0;
    *(uint4*)((char*)Bs + st_off + 64*80)    = pb1;
    __syncthreads();

    for (int ch = 0; ch < 32; ch++) {
        const int s = ch & 1;
        if (ch < 31) {
            const __half* Ap = Aptr + (ch + 1) * 32;
            const __half* Bp = Bptr + (ch + 1) * 32;
            pa0 = *(const uint4*)(Ap);
            pa1 = *(const uint4*)(Ap + (size_t)64 * KDIM);
            pb0 = *(const uint4*)(Bp);
            pb1 = *(const uint4*)(Bp + (size_t)64 * KDIM);
        }

        const uint32_t ab = asb + s * ABUF + a_l_off;
        const uint32_t bb = bsb + s * ABUF + b_l_off;
#pragma unroll
        for (int ks = 0; ks < 2; ks++) {
            uint32_t a[4][4];
            uint32_t b[4][2];
#pragma unroll
            for (int im = 0; im < 4; im++)
                LDSM4(a[im], ab + im * (16*80) + ks * 32);
#pragma unroll
            for (int jn = 0; jn < 4; jn++)
                asm volatile("ldmatrix.sync.aligned.m8n8.x2.shared.b16 {%0,%1}, [%2];"
                    : "=r"(b[jn][0]), "=r"(b[jn][1])
                    : "r"(bb + jn * (8*80) + ks * 32));
#pragma unroll
            for (int im = 0; im < 4; im++)
#pragma unroll
                for (int jn = 0; jn < 4; jn++)
                    MMA16816(c[im][jn], a[im], b[jn][0], b[jn][1]);
        }

        if (ch < 31) {
            const int s2 = s ^ 1;
            *(uint4*)((char*)As + s2*ABUF + st_off)         = pa0;
            *(uint4*)((char*)As + s2*ABUF + st_off + 64*80) = pa1;
            *(uint4*)((char*)Bs + s2*ABUF + st_off)         = pb0;
            *(uint4*)((char*)Bs + s2*ABUF + st_off + 64*80) = pb1;
            __syncthreads();
        }
    }

    const int g  = lane >> 2;
    const int tq = lane & 3;
#pragma unroll
    for (int im = 0; im < 4; im++) {
#pragma unroll
        for (int jn = 0; jn < 4; jn++) {
            const int row = row0 + wm*64 + im*16 + g;
            const int col = col0 + wn*32 + jn*8 + tq*2;
            if constexpr (sizeof(OT) == 2) {
                *(uint32_t*)((__half*)C + (size_t)row * Nc + col) =
                    pack_h2(c[im][jn][0], c[im][jn][1]);
                *(uint32_t*)((__half*)C + (size_t)(row + 8) * Nc + col) =
                    pack_h2(c[im][jn][2], c[im][jn][3]);
            } else {
                *(float2*)((float*)C + (size_t)row * Nc + col) =
                    make_float2(c[im][jn][0], c[im][jn][1]);
                *(float2*)((float*)C + (size_t)(row + 8) * Nc + col) =
                    make_float2(c[im][jn][2], c[im][jn][3]);
            }
        }
    }
}

// ============================================================
// HMMA causal flash attention (fp16 in, fp32 softmax, half out)
// CTA: 128 Q rows, 8 warps x 16 rows. K/V tiles 64, double-buffered.
// ============================================================
#define BQ 128
#define BK 64
#define KPAD 72      // halfs per smem row
#define KPADB 144    // bytes per smem row
#define QS_H  (BQ*KPAD)          // 9216 halfs
#define KVT_H (BK*KPAD)          // 4608 halfs per tile buffer
#define FSM2 ((QS_H + 4*KVT_H) * 2)   // bytes = 55296

__global__ __launch_bounds__(256) void flash_hmma(
    const __half* __restrict__ q, const __half* __restrict__ kv,
    __half* __restrict__ o)
{
    extern __shared__ __half sh[];
    __half* Qs = sh;
    __half* Ks = sh + QS_H;              // 2 buffers
    __half* Vs = sh + QS_H + 2*KVT_H;    // 2 buffers

    const int t = threadIdx.x, lane = t & 31, w = t >> 5;
    const int bq = blockIdx.x, bh = blockIdx.y;
    const int b = bh >> 4, h = bh & 15;
    const int row0 = bq * BQ;

    // load Q tile (128 rows x 64 halfs)
#pragma unroll
    for (int i = 0; i < 4; i++) {
        int e = t + i * 256;
        int r = e >> 3, qq = e & 7;
        *(uint4*)(Qs + r * KPAD + qq * 8) =
            *(const uint4*)(q + (size_t)(b*Nn + row0 + r) * HDd + h * DHh + qq * 8);
    }
    __syncthreads();

    // Q fragments (held in registers for whole kernel)
    uint32_t qf[4][4];
    {
        const uint32_t qb = smem_u32(Qs)
            + (uint32_t)((w*16 + (lane & 7) + ((lane >> 3) & 1) * 8) * KPADB
                         + ((lane >> 4) & 1) * 16);
#pragma unroll
        for (int ks = 0; ks < 4; ks++)
            LDSM4(qf[ks], qb + ks * 32);
    }

    const uint32_t ksb = smem_u32(Ks);
    const uint32_t vsb = smem_u32(Vs);
    // per-lane ldmatrix offsets
    const uint32_t k_off = (uint32_t)(((lane & 7) + ((lane >> 3) & 1) * 8) * KPADB
                                      + ((lane >> 4) & 1) * 16);

    float m_prev[2] = {-1e30f, -1e30f};
    float lsum[2]   = {0.f, 0.f};
    float oa[8][4];
#pragma unroll
    for (int jn = 0; jn < 8; jn++)
#pragma unroll
        for (int cc = 0; cc < 4; cc++) oa[jn][cc] = 0.f;

    const __half* kvbase = kv + (size_t)(b*Nn) * (2*HDd) + h * DHh;
    const int jt_max = row0 / BK + 1;   // inclusive

    // prolog: tile 0 -> buffer 0
    {
        int r = t >> 3, qq = t & 7;
        const __half* p0 = kvbase + (size_t)r * (2*HDd) + qq * 8;
        const __half* p1 = kvbase + (size_t)(r + 32) * (2*HDd) + qq * 8;
        uint4 k0 = *(const uint4*)p0, v0 = *(const uint4*)(p0 + HDd);
        uint4 k1 = *(const uint4*)p1, v1 = *(const uint4*)(p1 + HDd);
        *(uint4*)(Ks + r*KPAD + qq*8)        = k0;
        *(uint4*)(Ks + (r+32)*KPAD + qq*8)   = k1;
        *(uint4*)(Vs + r*KPAD + qq*8)        = v0;
        *(uint4*)(Vs + (r+32)*KPAD + qq*8)   = v1;
    }
    __syncthreads();

    const int rbase = row0 + w*16 + (lane >> 2);

    for (int jt = 0; jt <= jt_max; jt++) {
        const int s = jt & 1;
        uint4 nk0, nk1, nv0, nv1;
        if (jt < jt_max) {
            int r = t >> 3, qq = t & 7;
            const __half* p0 = kvbase + (size_t)((jt+1)*BK + r) * (2*HDd) + qq * 8;
            const __half* p1 = kvbase + (size_t)((jt+1)*BK + r + 32) * (2*HDd) + qq * 8;
            nk0 = *(const uint4*)p0; nv0 = *(const uint4*)(p0 + HDd);
            nk1 = *(const uint4*)p1; nv1 = *(const uint4*)(p1 + HDd);
        }

        const bool full_masked = (jt*BK > row0 + w*16 + 15);
        if (!full_masked) {
            // ---- S = Q K^T ----
            float sa[8][4];
#pragma unroll
            for (int jn = 0; jn < 8; jn++)
#pragma unroll
                for (int cc = 0; cc < 4; cc++) sa[jn][cc] = 0.f;

            const uint32_t kb = ksb + (uint32_t)s * (KVT_H*2) + k_off;
#pragma unroll
            for (int ks = 0; ks < 4; ks++) {
#pragma unroll
                for (int jp = 0; jp < 4; jp++) {
                    uint32_t kr[4];
                    LDSM4(kr, kb + jp * (16*KPADB) + ks * 32);
                    MMA16816(sa[2*jp],   qf[ks], kr[0], kr[2]);
                    MMA16816(sa[2*jp+1], qf[ks], kr[1], kr[3]);
                }
            }

            // ---- scale + causal mask ----
            const bool diag = (jt*BK + BK - 1 > row0 + w*16);
#pragma unroll
            for (int jn = 0; jn < 8; jn++)
#pragma unroll
                for (int cc = 0; cc < 4; cc++) {
                    sa[jn][cc] *= 0.125f;
                    if (diag) {
                        int col = jt*BK + jn*8 + (lane & 3)*2 + (cc & 1);
                        int row = rbase + (cc >> 1)*8;
                        if (col > row) sa[jn][cc] = -1e30f;
                    }
                }

            // ---- online softmax ----
            float rmax[2] = {-1e30f, -1e30f};
#pragma unroll
            for (int jn = 0; jn < 8; jn++) {
                rmax[0] = fmaxf(rmax[0], fmaxf(sa[jn][0], sa[jn][1]));
                rmax[1] = fmaxf(rmax[1], fmaxf(sa[jn][2], sa[jn][3]));
            }
#pragma unroll
            for (int k2 = 0; k2 < 2; k2++) {
                rmax[k2] = fmaxf(rmax[k2], __shfl_xor_sync(0xffffffffu, rmax[k2], 1));
                rmax[k2] = fmaxf(rmax[k2], __shfl_xor_sync(0xffffffffu, rmax[k2], 2));
            }
            float mnew[2]  = {fmaxf(m_prev[0], rmax[0]), fmaxf(m_prev[1], rmax[1])};
            float alpha[2] = {__expf(m_prev[0] - mnew[0]), __expf(m_prev[1] - mnew[1])};
            float rsum[2]  = {0.f, 0.f};
#pragma unroll
            for (int jn = 0; jn < 8; jn++)
#pragma unroll
                for (int cc = 0; cc < 4; cc++) {
                    sa[jn][cc] = __expf(sa[jn][cc] - mnew[cc >> 1]);
                    rsum[cc >> 1] += sa[jn][cc];
                }
#pragma unroll
            for (int k2 = 0; k2 < 2; k2++) {
                rsum[k2] += __shfl_xor_sync(0xffffffffu, rsum[k2], 1);
                rsum[k2] += __shfl_xor_sync(0xffffffffu, rsum[k2], 2);
                lsum[k2] = lsum[k2] * alpha[k2] + rsum[k2];
                m_prev[k2] = mnew[k2];
            }
#pragma unroll
            for (int jn = 0; jn < 8; jn++)
#pragma unroll
                for (int cc = 0; cc < 4; cc++) oa[jn][cc] *= alpha[cc >> 1];

            // ---- P -> A fragments (registers only) ----
            uint32_t pf[4][4];
#pragma unroll
            for (int ks = 0; ks < 4; ks++) {
                pf[ks][0] = pack_h2(sa[2*ks][0],   sa[2*ks][1]);
                pf[ks][1] = pack_h2(sa[2*ks][2],   sa[2*ks][3]);
                pf[ks][2] = pack_h2(sa[2*ks+1][0], sa[2*ks+1][1]);
                pf[ks][3] = pack_h2(sa[2*ks+1][2], sa[2*ks+1][3]);
            }

            // ---- O += P V ----
            const uint32_t vb = vsb + (uint32_t)s * (KVT_H*2) + k_off;
#pragma unroll
            for (int ks = 0; ks < 4; ks++) {
#pragma unroll
                for (int nb = 0; nb < 4; nb++) {
                    uint32_t vr[4];
                    LDSM4T(vr, vb + ks * (16*KPADB) + nb * 32);
                    MMA16816(oa[2*nb],   pf[ks], vr[0], vr[1]);
                    MMA16816(oa[2*nb+1], pf[ks], vr[2], vr[3]);
                }
            }
        }

        if (jt < jt_max) {
            __syncthreads();
            const int s2 = s ^ 1;
            int r = t >> 3, qq = t & 7;
            __half* kd = Ks + s2 * KVT_H;
            __half* vd = Vs + s2 * KVT_H;
            *(uint4*)(kd + r*KPAD + qq*8)      = nk0;
            *(uint4*)(kd + (r+32)*KPAD + qq*8) = nk1;
            *(uint4*)(vd + r*KPAD + qq*8)      = nv0;
            *(uint4*)(vd + (r+32)*KPAD + qq*8) = nv1;
            __syncthreads();
        }
    }

    // ---- epilogue ----
    float inv0 = 1.f / lsum[0], inv1 = 1.f / lsum[1];
    __half* ob = o + (size_t)(b*Nn + rbase) * HDd + h * DHh + (lane & 3) * 2;
#pragma unroll
    for (int jn = 0; jn < 8; jn++) {
        *(uint32_t*)(ob + jn*8)           = pack_h2(oa[jn][0]*inv0, oa[jn][1]*inv0);
        *(uint32_t*)(ob + 8*HDd + jn*8)   = pack_h2(oa[jn][2]*inv1, oa[jn][3]*inv1);
    }
}

// ============================================================
// launch
// ============================================================
extern "C" void kernel_launch(void* const* d_in, const int* in_sizes, int n_in,
                              void* d_out, int out_size)
{
    const float* x     = (const float*)d_in[0];
    const float* ln_g  = (const float*)d_in[1];
    const float* ln_b  = (const float*)d_in[2];
    const float* lnc_g = (const float*)d_in[3];
    const float* lnc_b = (const float*)d_in[4];
    const float* Wq    = (const float*)d_in[5];
    const float* Wkv   = (const float*)d_in[6];
    const float* Wo    = (const float*)d_in[7];
    float* out = (float*)d_out;

    __half *xn, *cn, *qp, *kvp, *aop, *wT;
    cudaGetSymbolAddress((void**)&xn,  g_xn);
    cudaGetSymbolAddress((void**)&cn,  g_cn);
    cudaGetSymbolAddress((void**)&qp,  g_q);
    cudaGetSymbolAddress((void**)&kvp, g_kv);
    cudaGetSymbolAddress((void**)&aop, g_ao);
    cudaGetSymbolAddress((void**)&wT,  g_wT);

    cudaFuncSetAttribute(flash_hmma,
                         cudaFuncAttributeMaxDynamicSharedMemorySize, FSM2);

    // 1) fused double layernorm (half outputs)
    ln2_kernel<<<Mm, 256>>>(x, ln_g, ln_b, lnc_g, lnc_b);

    // 2) q = xn @ Wq  (half out)
    transpose_h<<<dim3(HDd/32, Dd/32), dim3(32, 8)>>>(Wq, wT, Dd, HDd);
    gemm_hmma<__half><<<dim3(HDd/128, Mm/128), 256>>>(xn, wT, qp, HDd);

    // 3) kv = cn @ Wkv (half out)
    transpose_h<<<dim3(2*HDd/32, Dd/32), dim3(32, 8)>>>(Wkv, wT, Dd, 2*HDd);
    gemm_hmma<__half><<<dim3(2*HDd/128, Mm/128), 256>>>(cn, wT, kvp, 2*HDd);

    // 4) HMMA causal flash attention
    flash_hmma<<<dim3(Nn/BQ, Bb*Hh), 256, FSM2>>>(qp, kvp, aop);

    // 5) out = ao @ Wo (float out)
    transpose_h<<<dim3(Dd/32, HDd/32), dim3(32, 8)>>>(Wo, wT, HDd, Dd);
    gemm_hmma<float><<<dim3(Dd/128, Mm/128), 256>>>(aop, wT, out, Dd);
}

// round 5
// speedup vs baseline: 6.4473x; 1.1380x over previous
#include <cuda_runtime.h>
#include <cuda_fp16.h>
#include <math.h>
#include <cstdint>

#define Bb   2
#define Nn   2048
#define Dd   1024
#define Hh   16
#define DHh  64
#define Mm   (Bb*Nn)      // 4096 rows
#define HDd  (Hh*DHh)     // 1024
#define KDIM 1024
#define LNEPS 1e-5f

// ---- device scratch ----
__device__ __half g_xn[(size_t)Mm*Dd];
__device__ __half g_cn[(size_t)Mm*Dd];
__device__ __half g_q [(size_t)Mm*HDd];
__device__ __half g_kv[(size_t)Mm*2*HDd];
__device__ __half g_ao[(size_t)Mm*HDd];
__device__ __half g_wTq [(size_t)HDd*Dd];
__device__ __half g_wTkv[(size_t)2*HDd*Dd];
__device__ __half g_wTo [(size_t)Dd*HDd];

__device__ __forceinline__ uint32_t smem_u32(const void* p) {
    uint32_t a;
    asm("{ .reg .u64 t; cvta.to.shared.u64 t, %1; cvt.u32.u64 %0, t; }"
        : "=r"(a) : "l"(p));
    return a;
}

#define MMA16816(d, a, b0, b1) \
    asm volatile("mma.sync.aligned.m16n8k16.row.col.f32.f16.f16.f32 " \
        "{%0,%1,%2,%3}, {%4,%5,%6,%7}, {%8,%9}, {%0,%1,%2,%3};" \
        : "+f"((d)[0]), "+f"((d)[1]), "+f"((d)[2]), "+f"((d)[3]) \
        : "r"((a)[0]), "r"((a)[1]), "r"((a)[2]), "r"((a)[3]), \
          "r"(b0), "r"(b1))

#define LDSM4(r, addr) \
    asm volatile("ldmatrix.sync.aligned.m8n8.x4.shared.b16 {%0,%1,%2,%3}, [%4];" \
        : "=r"((r)[0]), "=r"((r)[1]), "=r"((r)[2]), "=r"((r)[3]) : "r"(addr))
#define LDSM4T(r, addr) \
    asm volatile("ldmatrix.sync.aligned.m8n8.x4.trans.shared.b16 {%0,%1,%2,%3}, [%4];" \
        : "=r"((r)[0]), "=r"((r)[1]), "=r"((r)[2]), "=r"((r)[3]) : "r"(addr))

#define CP16(dst_u32, src_ptr) \
    asm volatile("cp.async.cg.shared.global [%0], [%1], 16;" \
        :: "r"(dst_u32), "l"(src_ptr))
#define CP_COMMIT() asm volatile("cp.async.commit_group;" ::: "memory")
#define CP_WAIT(n)  asm volatile("cp.async.wait_group %0;" :: "n"(n) : "memory")

__device__ __forceinline__ uint32_t pack_h2(float a, float b) {
    __half2 h = __floats2half2_rn(a, b);
    return *(uint32_t*)&h;
}

// ============================================================
// Fused double LayerNorm -> half outputs
// ============================================================
__global__ __launch_bounds__(256) void ln2_kernel(
    const float* __restrict__ x,
    const float* __restrict__ g1, const float* __restrict__ b1,
    const float* __restrict__ g2, const float* __restrict__ b2)
{
    const int row = blockIdx.x;
    const float* xr = x + (size_t)row * Dd;
    const int t = threadIdx.x;

    float v[4]; float s = 0.f, ss = 0.f;
#pragma unroll
    for (int i = 0; i < 4; i++) {
        float val = xr[t + i*256];
        v[i] = val; s += val; ss += val*val;
    }
#pragma unroll
    for (int o = 16; o > 0; o >>= 1) {
        s  += __shfl_xor_sync(0xffffffffu, s,  o);
        ss += __shfl_xor_sync(0xffffffffu, ss, o);
    }
    __shared__ float rs[8], rss[8];
    const int w = t >> 5, l = t & 31;
    if (l == 0) { rs[w] = s; rss[w] = ss; }
    __syncthreads();
    if (t == 0) {
        float a = 0.f, c = 0.f;
        for (int i = 0; i < 8; i++) { a += rs[i]; c += rss[i]; }
        rs[0] = a; rss[0] = c;
    }
    __syncthreads();
    const float mean = rs[0] * (1.f/Dd);
    const float var  = rss[0] * (1.f/Dd) - mean*mean;
    const float rstd = rsqrtf(var + LNEPS);

    __half* xn = g_xn + (size_t)row*Dd;
    __half* cn = g_cn + (size_t)row*Dd;
#pragma unroll
    for (int i = 0; i < 4; i++) {
        int idx = t + i*256;
        float nv = (v[i] - mean) * rstd;
        xn[idx] = __float2half_rn(nv * g1[idx] + b1[idx]);
        cn[idx] = __float2half_rn(nv * g2[idx] + b2[idx]);
    }
}

// ============================================================
// All three weight transposes in one launch (grid.z selects)
// ============================================================
__global__ __launch_bounds__(256) void transpose_all(
    const float* __restrict__ Wq, const float* __restrict__ Wkv,
    const float* __restrict__ Wo)
{
    const int z = blockIdx.z;
    const float* W; __half* WT; int K, Nc;
    if (z == 0)      { W = Wq;  K = Dd;  Nc = HDd;   WT = g_wTq; }
    else if (z == 1) { W = Wkv; K = Dd;  Nc = 2*HDd; WT = g_wTkv; }
    else             { W = Wo;  K = HDd; Nc = Dd;    WT = g_wTo; }

    const int bn = blockIdx.x * 32, bk = blockIdx.y * 32;
    if (bn >= Nc) return;

    __shared__ float tile[32][33];
    const int x = threadIdx.x, y = threadIdx.y;
#pragma unroll
    for (int i = 0; i < 32; i += 8)
        tile[y + i][x] = W[(size_t)(bk + y + i) * Nc + bn + x];
    __syncthreads();
#pragma unroll
    for (int i = 0; i < 32; i += 8)
        WT[(size_t)(bn + y + i) * K + bk + x] = __float2half_rn(tile[x][y + i]);
}

// ============================================================
// fp16 HMMA GEMM, cp.async 4-stage pipeline.
// CTA 128x128, 4 warps (2x2), warp tile 64x64, K-chunk 32.
// smem stage: A 128x(32h pad 40h)=10240B, B same. 4 stages = 81920B.
// ============================================================
#define NSTAGE 4
#define CHUNKB 10240
#define GSMEM (NSTAGE*2*CHUNKB)

template <typename OT>
__global__ __launch_bounds__(128) void gemm_hmma(
    const __half* __restrict__ Ah, const __half* __restrict__ BTh,
    OT* __restrict__ C, int Nc)
{
    extern __shared__ char gsm[];
    const uint32_t asb = smem_u32(gsm);
    const uint32_t bsb = asb + NSTAGE*CHUNKB;

    const int t = threadIdx.x;
    const int lane = t & 31, wid = t >> 5;
    const int wm = wid >> 1, wn = wid & 1;
    const int row0 = blockIdx.y * 128, col0 = blockIdx.x * 128;

    const int r0 = t >> 2, c8 = t & 3;            // 128 threads: rows r0+32i
    const __half* Ap = Ah  + (size_t)(row0 + r0) * KDIM + c8 * 8;
    const __half* Bp = BTh + (size_t)(col0 + r0) * KDIM + c8 * 8;
    const uint32_t st_off = (uint32_t)(r0 * 80 + c8 * 16);

    const uint32_t a_l_off = (uint32_t)((wm*64 + (lane & 7) + ((lane >> 3) & 1) * 8) * 80
                                        + ((lane >> 4) & 1) * 16);
    const uint32_t b_l_off = (uint32_t)((wn*64 + (lane & 7) + ((lane >> 4) & 1) * 8) * 80
                                        + ((lane >> 3) & 1) * 16);

    float c[4][8][4];
#pragma unroll
    for (int i = 0; i < 4; i++)
#pragma unroll
        for (int j = 0; j < 8; j++)
#pragma unroll
            for (int q = 0; q < 4; q++) c[i][j][q] = 0.f;

    // prologue: chunks 0..2 -> stages 0..2
#pragma unroll
    for (int st = 0; st < 3; st++) {
#pragma unroll
        for (int i = 0; i < 4; i++) {
            CP16(asb + st*CHUNKB + st_off + i*(32*80), Ap + st*32 + (size_t)(32*i)*KDIM);
            CP16(bsb + st*CHUNKB + st_off + i*(32*80), Bp + st*32 + (size_t)(32*i)*KDIM);
        }
        CP_COMMIT();
    }

    for (int ch = 0; ch < 32; ch++) {
        CP_WAIT(2);
        __syncthreads();

        if (ch + 3 < 32) {
            const int st = (ch + 3) & 3;
#pragma unroll
            for (int i = 0; i < 4; i++) {
                CP16(asb + st*CHUNKB + st_off + i*(32*80), Ap + (ch+3)*32 + (size_t)(32*i)*KDIM);
                CP16(bsb + st*CHUNKB + st_off + i*(32*80), Bp + (ch+3)*32 + (size_t)(32*i)*KDIM);
            }
        }
        CP_COMMIT();

        const uint32_t ab = asb + (ch & 3)*CHUNKB + a_l_off;
        const uint32_t bb = bsb + (ch & 3)*CHUNKB + b_l_off;
#pragma unroll
        for (int ks = 0; ks < 2; ks++) {
            uint32_t a[4][4], b[4][4];
#pragma unroll
            for (int im = 0; im < 4; im++)
                LDSM4(a[im], ab + im * (16*80) + ks * 32);
#pragma unroll
            for (int jq = 0; jq < 4; jq++)
                LDSM4(b[jq], bb + jq * (16*80) + ks * 32);
#pragma unroll
            for (int im = 0; im < 4; im++)
#pragma unroll
                for (int jq = 0; jq < 4; jq++) {
                    MMA16816(c[im][2*jq],   a[im], b[jq][0], b[jq][1]);
                    MMA16816(c[im][2*jq+1], a[im], b[jq][2], b[jq][3]);
                }
        }
    }

    const int g  = lane >> 2;
    const int tq = lane & 3;
#pragma unroll
    for (int im = 0; im < 4; im++) {
#pragma unroll
        for (int jn = 0; jn < 8; jn++) {
            const int row = row0 + wm*64 + im*16 + g;
            const int col = col0 + wn*64 + jn*8 + tq*2;
            if constexpr (sizeof(OT) == 2) {
                *(uint32_t*)((__half*)C + (size_t)row * Nc + col) =
                    pack_h2(c[im][jn][0], c[im][jn][1]);
                *(uint32_t*)((__half*)C + (size_t)(row + 8) * Nc + col) =
                    pack_h2(c[im][jn][2], c[im][jn][3]);
            } else {
                *(float2*)((float*)C + (size_t)row * Nc + col) =
                    make_float2(c[im][jn][0], c[im][jn][1]);
                *(float2*)((float*)C + (size_t)(row + 8) * Nc + col) =
                    make_float2(c[im][jn][2], c[im][jn][3]);
            }
        }
    }
}

// ============================================================
// HMMA causal flash attention, cp.async 3-buffer KV ring.
// CTA: 128 Q rows, 8 warps x 16 rows. KV tiles of 64 tokens.
// ============================================================
#define BQ 128
#define BK 64
#define KPAD 72
#define KPADB 144
#define QS_H  (BQ*KPAD)            // 9216 halfs
#define KVT_H (BK*KPAD)            // 4608 halfs per buffer
#define FSM2 ((QS_H + 6*KVT_H) * 2)  // 73728 bytes
#define SOFT_SCALE (0.125f * 1.44269504088896f)   // 1/sqrt(64) * log2(e)

__global__ __launch_bounds__(256) void flash_hmma(
    const __half* __restrict__ q, const __half* __restrict__ kv,
    __half* __restrict__ o)
{
    extern __shared__ __half sh[];
    __half* Qs = sh;

    const int t = threadIdx.x, lane = t & 31, w = t >> 5;
    const int bq = blockIdx.x, bh = blockIdx.y;
    const int b = bh >> 4, h = bh & 15;
    const int row0 = bq * BQ;

    const uint32_t shb = smem_u32(sh);
    const uint32_t ksb = shb + QS_H*2;                // 3 K buffers
    const uint32_t vsb = ksb + 3*KVT_H*2;             // 3 V buffers

    // load Q tile (plain, once)
#pragma unroll
    for (int i = 0; i < 4; i++) {
        int e = t + i * 256;
        int r = e >> 3, qq = e & 7;
        *(uint4*)(Qs + r * KPAD + qq * 8) =
            *(const uint4*)(q + (size_t)(b*Nn + row0 + r) * HDd + h * DHh + qq * 8);
    }

    const __half* kvbase = kv + (size_t)(b*Nn) * (2*HDd) + h * DHh;
    const int jt_max = row0 / BK + 1;

    const int lr = t >> 3, lq = t & 7;   // cp.async mapping: rows lr, lr+32
    auto issue_kv = [&](int jt, int buf) {
        const __half* p0 = kvbase + (size_t)(jt*BK + lr) * (2*HDd) + lq * 8;
        const __half* p1 = p0 + (size_t)32 * (2*HDd);
        const uint32_t kd = ksb + (uint32_t)buf * (KVT_H*2);
        const uint32_t vd = vsb + (uint32_t)buf * (KVT_H*2);
        CP16(kd + lr*KPADB + lq*16,        p0);
        CP16(kd + (lr+32)*KPADB + lq*16,   p1);
        CP16(vd + lr*KPADB + lq*16,        p0 + HDd);
        CP16(vd + (lr+32)*KPADB + lq*16,   p1 + HDd);
    };

    // prologue: tiles 0 and 1 (jt_max >= 1 always)
    issue_kv(0, 0); CP_COMMIT();
    issue_kv(1, 1); CP_COMMIT();

    __syncthreads();   // Q ready

    // Q fragments in registers
    uint32_t qf[4][4];
    {
        const uint32_t qb = shb
            + (uint32_t)((w*16 + (lane & 7) + ((lane >> 3) & 1) * 8) * KPADB
                         + ((lane >> 4) & 1) * 16);
#pragma unroll
        for (int ks = 0; ks < 4; ks++)
            LDSM4(qf[ks], qb + ks * 32);
    }

    const uint32_t k_off = (uint32_t)(((lane & 7) + ((lane >> 3) & 1) * 8) * KPADB
                                      + ((lane >> 4) & 1) * 16);

    float m_prev[2] = {-1e30f, -1e30f};
    float lsum[2]   = {0.f, 0.f};
    float oa[8][4];
#pragma unroll
    for (int jn = 0; jn < 8; jn++)
#pragma unroll
        for (int cc = 0; cc < 4; cc++) oa[jn][cc] = 0.f;

    const int rbase = row0 + w*16 + (lane >> 2);

    for (int jt = 0; jt <= jt_max; jt++) {
        CP_WAIT(1);
        __syncthreads();

        if (jt + 2 <= jt_max) issue_kv(jt + 2, (jt + 2) % 3);
        CP_COMMIT();

        const bool full_masked = (jt*BK > row0 + w*16 + 15);
        if (!full_masked) {
            const int buf = jt % 3;
            // ---- S = Q K^T ----
            float sa[8][4];
#pragma unroll
            for (int jn = 0; jn < 8; jn++)
#pragma unroll
                for (int cc = 0; cc < 4; cc++) sa[jn][cc] = 0.f;

            const uint32_t kb = ksb + (uint32_t)buf * (KVT_H*2) + k_off;
#pragma unroll
            for (int ks = 0; ks < 4; ks++) {
#pragma unroll
                for (int jp = 0; jp < 4; jp++) {
                    uint32_t kr[4];
                    LDSM4(kr, kb + jp * (16*KPADB) + ks * 32);
                    MMA16816(sa[2*jp],   qf[ks], kr[0], kr[2]);
                    MMA16816(sa[2*jp+1], qf[ks], kr[1], kr[3]);
                }
            }

            // ---- scale (exp2 domain) + causal mask ----
            const bool diag = (jt*BK + BK - 1 > row0 + w*16);
#pragma unroll
            for (int jn = 0; jn < 8; jn++)
#pragma unroll
                for (int cc = 0; cc < 4; cc++) {
                    sa[jn][cc] *= SOFT_SCALE;
                    if (diag) {
                        int col = jt*BK + jn*8 + (lane & 3)*2 + (cc & 1);
                        int row = rbase + (cc >> 1)*8;
                        if (col > row) sa[jn][cc] = -1e30f;
                    }
                }

            // ---- online softmax (base-2) ----
            float rmax[2] = {-1e30f, -1e30f};
#pragma unroll
            for (int jn = 0; jn < 8; jn++) {
                rmax[0] = fmaxf(rmax[0], fmaxf(sa[jn][0], sa[jn][1]));
                rmax[1] = fmaxf(rmax[1], fmaxf(sa[jn][2], sa[jn][3]));
            }
#pragma unroll
            for (int k2 = 0; k2 < 2; k2++) {
                rmax[k2] = fmaxf(rmax[k2], __shfl_xor_sync(0xffffffffu, rmax[k2], 1));
                rmax[k2] = fmaxf(rmax[k2], __shfl_xor_sync(0xffffffffu, rmax[k2], 2));
            }
            float mnew[2]  = {fmaxf(m_prev[0], rmax[0]), fmaxf(m_prev[1], rmax[1])};
            float alpha[2] = {exp2f(m_prev[0] - mnew[0]), exp2f(m_prev[1] - mnew[1])};
            float rsum[2]  = {0.f, 0.f};
#pragma unroll
            for (int jn = 0; jn < 8; jn++)
#pragma unroll
                for (int cc = 0; cc < 4; cc++) {
                    sa[jn][cc] = exp2f(sa[jn][cc] - mnew[cc >> 1]);
                    rsum[cc >> 1] += sa[jn][cc];
                }
#pragma unroll
            for (int k2 = 0; k2 < 2; k2++) {
                rsum[k2] += __shfl_xor_sync(0xffffffffu, rsum[k2], 1);
                rsum[k2] += __shfl_xor_sync(0xffffffffu, rsum[k2], 2);
                lsum[k2] = lsum[k2] * alpha[k2] + rsum[k2];
                m_prev[k2] = mnew[k2];
            }
#pragma unroll
            for (int jn = 0; jn < 8; jn++)
#pragma unroll
                for (int cc = 0; cc < 4; cc++) oa[jn][cc] *= alpha[cc >> 1];

            // ---- P -> A fragments ----
            uint32_t pf[4][4];
#pragma unroll
            for (int ks = 0; ks < 4; ks++) {
                pf[ks][0] = pack_h2(sa[2*ks][0],   sa[2*ks][1]);
                pf[ks][1] = pack_h2(sa[2*ks][2],   sa[2*ks][3]);
                pf[ks][2] = pack_h2(sa[2*ks+1][0], sa[2*ks+1][1]);
                pf[ks][3] = pack_h2(sa[2*ks+1][2], sa[2*ks+1][3]);
            }

            // ---- O += P V ----
            const uint32_t vb = vsb + (uint32_t)buf * (KVT_H*2) + k_off;
#pragma unroll
            for (int ks = 0; ks < 4; ks++) {
#pragma unroll
                for (int nb = 0; nb < 4; nb++) {
                    uint32_t vr[4];
                    LDSM4T(vr, vb + ks * (16*KPADB) + nb * 32);
                    MMA16816(oa[2*nb],   pf[ks], vr[0], vr[1]);
                    MMA16816(oa[2*nb+1], pf[ks], vr[2], vr[3]);
                }
            }
        }
    }

    // ---- epilogue ----
    float inv0 = 1.f / lsum[0], inv1 = 1.f / lsum[1];
    __half* ob = o + (size_t)(b*Nn + rbase) * HDd + h * DHh + (lane & 3) * 2;
#pragma unroll
    for (int jn = 0; jn < 8; jn++) {
        *(uint32_t*)(ob + jn*8)           = pack_h2(oa[jn][0]*inv0, oa[jn][1]*inv0);
        *(uint32_t*)(ob + 8*HDd + jn*8)   = pack_h2(oa[jn][2]*inv1, oa[jn][3]*inv1);
    }
}

// ============================================================
// launch
// ============================================================
extern "C" void kernel_launch(void* const* d_in, const int* in_sizes, int n_in,
                              void* d_out, int out_size)
{
    const float* x     = (const float*)d_in[0];
    const float* ln_g  = (const float*)d_in[1];
    const float* ln_b  = (const float*)d_in[2];
    const float* lnc_g = (const float*)d_in[3];
    const float* lnc_b = (const float*)d_in[4];
    const float* Wq    = (const float*)d_in[5];
    const float* Wkv   = (const float*)d_in[6];
    const float* Wo    = (const float*)d_in[7];
    float* out = (float*)d_out;

    __half *xn, *cn, *qp, *kvp, *aop, *wTq, *wTkv, *wTo;
    cudaGetSymbolAddress((void**)&xn,   g_xn);
    cudaGetSymbolAddress((void**)&cn,   g_cn);
    cudaGetSymbolAddress((void**)&qp,   g_q);
    cudaGetSymbolAddress((void**)&kvp,  g_kv);
    cudaGetSymbolAddress((void**)&aop,  g_ao);
    cudaGetSymbolAddress((void**)&wTq,  g_wTq);
    cudaGetSymbolAddress((void**)&wTkv, g_wTkv);
    cudaGetSymbolAddress((void**)&wTo,  g_wTo);

    cudaFuncSetAttribute(flash_hmma,
                         cudaFuncAttributeMaxDynamicSharedMemorySize, FSM2);
    cudaFuncSetAttribute(gemm_hmma<__half>,
                         cudaFuncAttributeMaxDynamicSharedMemorySize, GSMEM);
    cudaFuncSetAttribute(gemm_hmma<float>,
                         cudaFuncAttributeMaxDynamicSharedMemorySize, GSMEM);

    // 1) all weight transposes (one launch)
    transpose_all<<<dim3(2*HDd/32, Dd/32, 3), dim3(32, 8)>>>(Wq, Wkv, Wo);
    // 2) fused double layernorm (half outputs)
    ln2_kernel<<<Mm, 256>>>(x, ln_g, ln_b, lnc_g, lnc_b);
    // 3) q = xn @ Wq
    gemm_hmma<__half><<<dim3(HDd/128, Mm/128), 128, GSMEM>>>(xn, wTq, qp, HDd);
    // 4) kv = cn @ Wkv
    gemm_hmma<__half><<<dim3(2*HDd/128, Mm/128), 128, GSMEM>>>(cn, wTkv, kvp, 2*HDd);
    // 5) HMMA causal flash attention
    flash_hmma<<<dim3(Nn/BQ, Bb*Hh), 256, FSM2>>>(qp, kvp, aop);
    // 6) out = ao @ Wo
    gemm_hmma<float><<<dim3(Dd/128, Mm/128), 128, GSMEM>>>(aop, wTo, out, Dd);
}